// round 5
// baseline (speedup 1.0000x reference)
#include <cuda_runtime.h>
#include <cooperative_groups.h>
#include <math.h>
#include <stdint.h>

namespace cg = cooperative_groups;

#define BATCH 64
#define NN    256
#define MM    512
#define SIGMA 1e-6f
#define RHO   0.1f
#define ALPHA 1.6f
#define ITERS 200
#define TRI   32896   // 256*257/2
#define RR    80      // Y rows resident in SMEM per half-CTA (of 128)

__device__ float g_M[BATCH * TRI];
__device__ float g_Linv[BATCH * TRI];
__device__ float g_Y[BATCH * NN * MM];
__device__ float g_g[BATCH * NN];
__device__ float g_S[BATCH * NN];

__device__ __forceinline__ int offr(int i) { return (i * (i + 1)) >> 1; }
__constant__ int c_ti[10] = {0,1,1,2,2,2,3,3,3,3};
__constant__ int c_tj[10] = {0,0,1,0,1,2,0,1,2,3};

__device__ __forceinline__ uint32_t smem_u32(const void* p) {
    uint32_t a;
    asm("{ .reg .u64 t; cvta.to.shared.u64 t, %1; cvt.u32.u64 %0, t; }"
        : "=r"(a) : "l"(p));
    return a;
}

// K1: M = diag(P)+sigma*I+rho*A^T A (packed lower). 64x64 tiles, 4x4 regs.
__global__ __launch_bounds__(256) void k1_buildM(const float* __restrict__ Pv,
                                                 const float* __restrict__ Av)
{
    int p = blockIdx.x, b = blockIdx.y;
    int i0 = c_ti[p] * 64, j0 = c_tj[p] * 64;
    __shared__ float As[16][64], Bs[16][64];
    const float* A = Av + (size_t)b * (MM * NN);
    float acc[4][4];
#pragma unroll
    for (int a = 0; a < 4; a++)
#pragma unroll
        for (int c = 0; c < 4; c++) acc[a][c] = 0.f;
    int t = threadIdx.x, tx = t & 15, ty = t >> 4;
    for (int k0 = 0; k0 < MM; k0 += 16) {
#pragma unroll
        for (int r = 0; r < 4; r++) {
            int idx = t + 256 * r, kk = idx >> 6, ii = idx & 63;
            As[kk][ii] = A[(k0 + kk) * NN + i0 + ii];
            Bs[kk][ii] = A[(k0 + kk) * NN + j0 + ii];
        }
        __syncthreads();
#pragma unroll
        for (int kk = 0; kk < 16; kk++) {
            float a[4], c[4];
#pragma unroll
            for (int x = 0; x < 4; x++) { a[x] = As[kk][ty + 16 * x]; c[x] = Bs[kk][tx + 16 * x]; }
#pragma unroll
            for (int ii = 0; ii < 4; ii++)
#pragma unroll
                for (int jj = 0; jj < 4; jj++) acc[ii][jj] = fmaf(a[ii], c[jj], acc[ii][jj]);
        }
        __syncthreads();
    }
    float* Mb = g_M + (size_t)b * TRI;
#pragma unroll
    for (int ii = 0; ii < 4; ii++) {
        int i = i0 + ty + 16 * ii;
#pragma unroll
        for (int jj = 0; jj < 4; jj++) {
            int j = j0 + tx + 16 * jj;
            if (j <= i) {
                float vv = RHO * acc[ii][jj];
                if (i == j) vv += Pv[b * NN + i] + SIGMA;
                Mb[offr(i) + j] = vv;
            }
        }
    }
}

// K2: per-batch Cholesky in SMEM (packed, rank-1 updates)
__global__ __launch_bounds__(1024) void k2_chol()
{
    int b = blockIdx.x, tid = threadIdx.x;
    extern __shared__ float sm2[];
    float* Ls = sm2;
    float* col = sm2 + TRI;
    float* Mb = g_M + (size_t)b * TRI;
    for (int i = tid; i < TRI; i += 1024) Ls[i] = Mb[i];
    __syncthreads();
    int lane = tid & 31, w = tid >> 5;
    for (int k = 0; k < 256; k++) {
        float dkk = Ls[offr(k) + k];
        float s = sqrtf(dkk), rinv = 1.0f / s;
        __syncthreads();
        for (int i = k + tid; i < 256; i += 1024) {
            if (i == k) { Ls[offr(k) + k] = s; col[k] = s; }
            else { float vv = Ls[offr(i) + k] * rinv; Ls[offr(i) + k] = vv; col[i] = vv; }
        }
        __syncthreads();
        for (int i = k + 1 + w; i < 256; i += 32) {
            float ci = col[i];
            float* row = Ls + offr(i);
            for (int j = k + 1 + lane; j <= i; j += 32) row[j] = fmaf(-ci, col[j], row[j]);
        }
        __syncthreads();
    }
    for (int i = tid; i < TRI; i += 1024) Mb[i] = Ls[i];
}

// K3: Linv = L^{-1}, warp per column
__global__ __launch_bounds__(1024) void k3_trinv()
{
    int b = blockIdx.x, tid = threadIdx.x;
    extern __shared__ float sm3[];
    float* Ls = sm3;
    float* cb0 = sm3 + TRI;
    const float* Mb = g_M + (size_t)b * TRI;
    float* Lb = g_Linv + (size_t)b * TRI;
    for (int i = tid; i < TRI; i += 1024) Ls[i] = Mb[i];
    __syncthreads();
    int lane = tid & 31, w = tid >> 5;
    float* cb = cb0 + w * 256;
    for (int kc = w; kc < 256; kc += 32) {
        if (lane == 0) cb[kc] = 1.0f / Ls[offr(kc) + kc];
        __syncwarp();
        for (int i = kc + 1; i < 256; i++) {
            const float* row = Ls + offr(i);
            float s = 0.f;
            for (int j = kc + lane; j < i; j += 32) s = fmaf(row[j], cb[j], s);
#pragma unroll
            for (int o = 16; o; o >>= 1) s += __shfl_xor_sync(0xFFFFFFFFu, s, o);
            if (lane == 0) cb[i] = -s / row[i];
            __syncwarp();
        }
        for (int i = kc + lane; i < 256; i += 32) Lb[offr(i) + kc] = cb[i];
    }
}

// K4: Y[n][m] = sum_{j<=n} Linv[n][j]*A[m][j]
__global__ __launch_bounds__(256) void k4_Y(const float* __restrict__ Av)
{
    int b = blockIdx.z;
    int m0 = blockIdx.x * 64, n0 = blockIdx.y * 64;
    __shared__ float As[16][65], Bs[16][65];
    const float* Lb = g_Linv + (size_t)b * TRI;
    const float* A = Av + (size_t)b * (MM * NN);
    float acc[4][4];
#pragma unroll
    for (int a = 0; a < 4; a++)
#pragma unroll
        for (int c = 0; c < 4; c++) acc[a][c] = 0.f;
    int t = threadIdx.x, tx = t & 15, ty = t >> 4;
    int kmax = n0 + 64;
    for (int k0 = 0; k0 < kmax; k0 += 16) {
#pragma unroll
        for (int r = 0; r < 4; r++) {
            int idx = t + 256 * r, jj = idx & 15, nn = idx >> 4;
            int n = n0 + nn, j = k0 + jj;
            As[jj][nn] = (j <= n) ? Lb[offr(n) + j] : 0.f;
            Bs[jj][nn] = A[(m0 + nn) * NN + j];
        }
        __syncthreads();
#pragma unroll
        for (int jj = 0; jj < 16; jj++) {
            float a[4], c[4];
#pragma unroll
            for (int x = 0; x < 4; x++) { a[x] = As[jj][ty + 16 * x]; c[x] = Bs[jj][tx + 16 * x]; }
#pragma unroll
            for (int ii = 0; ii < 4; ii++)
#pragma unroll
                for (int cc = 0; cc < 4; cc++) acc[ii][cc] = fmaf(a[ii], c[cc], acc[ii][cc]);
        }
        __syncthreads();
    }
#pragma unroll
    for (int ii = 0; ii < 4; ii++) {
        int n = n0 + ty + 16 * ii;
#pragma unroll
        for (int cc = 0; cc < 4; cc++) {
            int m = m0 + tx + 16 * cc;
            g_Y[((size_t)b * NN + n) * MM + m] = acc[ii][cc];
        }
    }
}

// K4b: g = Linv * q
__global__ __launch_bounds__(256) void k4b_g(const float* __restrict__ qv)
{
    int b = blockIdx.x, tid = threadIdx.x;
    __shared__ float sq[NN];
    sq[tid] = qv[b * NN + tid];
    __syncthreads();
    int lane = tid & 31, w = tid >> 5;
    const float* Lb = g_Linv + (size_t)b * TRI;
    for (int i = w; i < NN; i += 8) {
        const float* row = Lb + offr(i);
        float s = 0.f;
        for (int j = lane; j <= i; j += 32) s = fmaf(row[j], sq[j], s);
#pragma unroll
        for (int o = 16; o; o >>= 1) s += __shfl_xor_sync(0xFFFFFFFFu, s, o);
        if (lane == 0) g_g[b * NN + i] = s;
    }
}

// K5: 200 ADMM iterations. 2-CTA cluster per batch item; each CTA owns 128 Y rows
// (80 SMEM-resident), single-row pipeline, mbarrier ping-pong instead of cluster.sync.
#define SM5_FLOATS (4 + RR * 512 + 16 * 512 + 4 * 512 + 2 * 512)
__global__ __cluster_dims__(2, 1, 1) __launch_bounds__(512, 1)
void k5_iter(const float* __restrict__ lv, const float* __restrict__ uv)
{
    cg::cluster_group cluster = cg::this_cluster();
    int b = blockIdx.x >> 1, half = blockIdx.x & 1;
    int tid = threadIdx.x, lane = tid & 31, w = tid >> 5;
    extern __shared__ float sm5[];
    float* mbf  = sm5;                    // 2 x u64 mbarriers (4 floats)
    float* sY   = sm5 + 4;                // RR*512
    float* red  = sY + RR * 512;          // 16*512
    float* sz   = red + 16 * 512;         // 512
    float* sy   = sz + 512;               // 512
    float* sl   = sy + 512;               // 512
    float* sub  = sl + 512;               // 512
    float* sbuf = sub + 512;              // 2*512 (peer writes here)

    uint32_t mb_u32 = smem_u32(mbf);
    if (tid == 0) {
        asm volatile("mbarrier.init.shared.b64 [%0], %1;" :: "r"(mb_u32), "r"(512) : "memory");
        asm volatile("mbarrier.init.shared.b64 [%0], %1;" :: "r"(mb_u32 + 8), "r"(512) : "memory");
    }

    const float* Yg = g_Y + ((size_t)b * NN + half * 128) * MM;
    const float4* Yg4 = (const float4*)Yg;
    for (int i = tid; i < RR * 128; i += 512)
        ((float4*)sY)[i] = Yg4[i];
    sz[tid] = 0.f; sy[tid] = 0.f;
    sl[tid] = lv[b * MM + tid]; sub[tid] = uv[b * MM + tid];

    // rows owned by this warp: n = w + 16*r, r=0..7 (r<5 resident since w<16 -> n<80)
    float Sreg[8], gre[8];
#pragma unroll
    for (int r = 0; r < 8; r++) {
        Sreg[r] = 0.f;
        gre[r] = g_g[b * NN + half * 128 + w + 16 * r];
    }
    cluster.sync();   // one-time: barrier init visible, staging done

    uint32_t peer = (uint32_t)(half ^ 1);
    float* peerbuf = cluster.map_shared_rank(sbuf, peer);
    const float4* sY4 = (const float4*)sY;
    const float4* z4 = (const float4*)sz;
    const float4* yv4 = (const float4*)sy;
    float4* redw = (float4*)(red + w * 512);

    for (int it = 0; it < ITERS; it++) {
        __syncthreads();   // sz/sy stable; red free for reuse
        float4 ul[4];
#pragma unroll
        for (int c = 0; c < 4; c++) {
            float4 zz = z4[lane * 4 + c], yy = yv4[lane * 4 + c];
            ul[c].x = RHO * zz.x - yy.x; ul[c].y = RHO * zz.y - yy.y;
            ul[c].z = RHO * zz.z - yy.z; ul[c].w = RHO * zz.w - yy.w;
        }
        float4 acc[4];
#pragma unroll
        for (int c = 0; c < 4; c++) acc[c] = make_float4(0.f, 0.f, 0.f, 0.f);

        float4 yb[2][4];
#pragma unroll
        for (int c = 0; c < 4; c++) yb[0][c] = sY4[(size_t)w * 128 + lane * 4 + c];

#pragma unroll
        for (int r = 0; r < 8; r++) {
            if (r < 7) {   // prefetch next row
                int n1 = w + 16 * (r + 1);
                bool res1 = (r + 1) < 5;
#pragma unroll
                for (int c = 0; c < 4; c++) {
                    if (res1) yb[(r + 1) & 1][c] = sY4[(size_t)n1 * 128 + lane * 4 + c];
                    else      yb[(r + 1) & 1][c] = Yg4[(size_t)n1 * 128 + lane * 4 + c];
                }
            }
            float4* y = yb[r & 1];
            float s = 0.f;
#pragma unroll
            for (int c = 0; c < 4; c++)
                s += y[c].x * ul[c].x + y[c].y * ul[c].y + y[c].z * ul[c].z + y[c].w * ul[c].w;
#pragma unroll
            for (int o = 16; o; o >>= 1) s += __shfl_xor_sync(0xFFFFFFFFu, s, o);
            s -= gre[r];
            Sreg[r] = (1.0f - ALPHA) * Sreg[r] + ALPHA * s;
#pragma unroll
            for (int c = 0; c < 4; c++) {
                acc[c].x = fmaf(s, y[c].x, acc[c].x);
                acc[c].y = fmaf(s, y[c].y, acc[c].y);
                acc[c].z = fmaf(s, y[c].z, acc[c].z);
                acc[c].w = fmaf(s, y[c].w, acc[c].w);
            }
        }
#pragma unroll
        for (int c = 0; c < 4; c++) redw[lane * 4 + c] = acc[c];
        __syncthreads();
        float mypart = 0.f;
#pragma unroll
        for (int w2 = 0; w2 < 16; w2++) mypart += red[w2 * 512 + tid];

        int slot = it & 1;
        uint32_t par = (uint32_t)((it >> 1) & 1);
        peerbuf[slot * 512 + tid] = mypart;           // DSMEM store
        // release-arrive on peer's mbarrier (orders the store above, cluster scope)
        asm volatile(
            "{ .reg .b32 rem; mapa.shared::cluster.u32 rem, %0, %1;\n\t"
            "mbarrier.arrive.release.cluster.shared::cluster.b64 _, [rem]; }"
            :: "r"(mb_u32 + 8 * slot), "r"(peer) : "memory");
        // acquire-wait on my mbarrier for peer's 512 arrivals
        {
            uint32_t addr = mb_u32 + 8 * slot, done;
            asm volatile(
                "{ .reg .pred p;\n\t"
                "mbarrier.try_wait.parity.acquire.cluster.shared::cta.b64 p, [%1], %2;\n\t"
                "selp.b32 %0, 1, 0, p; }"
                : "=r"(done) : "r"(addr), "r"(par) : "memory");
            if (!done) {
                asm volatile(
                    "{ .reg .pred P1;\n\t"
                    "WL_%=:\n\t"
                    "mbarrier.try_wait.parity.acquire.cluster.shared::cta.b64 P1, [%0], %1, 0x989680;\n\t"
                    "@P1 bra.uni WD_%=;\n\t"
                    "bra.uni WL_%=;\n\t"
                    "WD_%=: }"
                    :: "r"(addr), "r"(par) : "memory");
            }
        }
        float zt = mypart + sbuf[slot * 512 + tid];
        float zr = ALPHA * zt + (1.0f - ALPHA) * sz[tid];
        float zc = zr + sy[tid] * (1.0f / RHO);
        float zn = fminf(fmaxf(zc, sl[tid]), sub[tid]);
        sy[tid] = sy[tid] + RHO * (zr - zn);
        sz[tid] = zn;
    }
    if (lane == 0) {
#pragma unroll
        for (int r = 0; r < 8; r++)
            g_S[b * NN + half * 128 + w + 16 * r] = Sreg[r];
    }
    cluster.sync();   // don't exit while peer may still write our sbuf
}

// K6: x = Linv^T * S  -> d_out
__global__ __launch_bounds__(256) void k6_final(float* __restrict__ out)
{
    int b = blockIdx.x, tid = threadIdx.x;
    int lane = tid & 31, w = tid >> 5;
    __shared__ float sS[NN];
    __shared__ float red6[8][NN];
    sS[tid] = g_S[b * NN + tid];
    __syncthreads();
    const float* Lb = g_Linv + (size_t)b * TRI;
    float acc[8];
#pragma unroll
    for (int c = 0; c < 8; c++) acc[c] = 0.f;
    for (int n = w; n < NN; n += 8) {
        const float* row = Lb + offr(n);
        float sv = sS[n];
#pragma unroll
        for (int c = 0; c < 8; c++) {
            int i = lane + 32 * c;
            if (i <= n) acc[c] = fmaf(sv, row[i], acc[c]);
        }
    }
#pragma unroll
    for (int c = 0; c < 8; c++) red6[w][lane + 32 * c] = acc[c];
    __syncthreads();
    float x = 0.f;
#pragma unroll
    for (int w2 = 0; w2 < 8; w2++) x += red6[w2][tid];
    out[b * NN + tid] = x;
}

extern "C" void kernel_launch(void* const* d_in, const int* in_sizes, int n_in,
                              void* d_out, int out_size)
{
    const float* P = (const float*)d_in[0];
    const float* q = (const float*)d_in[1];
    const float* A = (const float*)d_in[2];
    const float* l = (const float*)d_in[3];
    const float* u = (const float*)d_in[4];
    float* out = (float*)d_out;

    int smem_k2 = (TRI + 256) * 4;
    int smem_k3 = (TRI + 32 * 256) * 4;
    int smem_k5 = SM5_FLOATS * 4;   // 208,912 B
    cudaFuncSetAttribute(k2_chol, cudaFuncAttributeMaxDynamicSharedMemorySize, smem_k2);
    cudaFuncSetAttribute(k3_trinv, cudaFuncAttributeMaxDynamicSharedMemorySize, smem_k3);
    cudaFuncSetAttribute(k5_iter, cudaFuncAttributeMaxDynamicSharedMemorySize, smem_k5);

    k1_buildM<<<dim3(10, BATCH), 256>>>(P, A);
    k2_chol<<<BATCH, 1024, smem_k2>>>();
    k3_trinv<<<BATCH, 1024, smem_k3>>>();
    k4_Y<<<dim3(8, 4, BATCH), 256>>>(A);
    k4b_g<<<BATCH, 256>>>(q);
    k5_iter<<<BATCH * 2, 512, smem_k5>>>(l, u);
    k6_final<<<BATCH, 256>>>(out);
}

// round 7
// speedup vs baseline: 1.0345x; 1.0345x over previous
#include <cuda_runtime.h>
#include <cooperative_groups.h>
#include <math.h>
#include <stdint.h>

namespace cg = cooperative_groups;

#define BATCH 64
#define NN    256
#define MM    512
#define SIGMA 1e-6f
#define RHO   0.1f
#define ALPHA 1.6f
#define ITERS 200
#define TRI   32896   // 256*257/2
#define RR    80      // Y rows resident in SMEM per half-CTA (of 128)

__device__ float g_Linv[BATCH * TRI];
__device__ float g_M[BATCH * TRI];
__device__ float g_Y[BATCH * NN * MM];
__device__ float g_S[BATCH * NN];

__device__ __forceinline__ int offr(int i) { return (i * (i + 1)) >> 1; }
__constant__ int c_ti[10] = {0,1,1,2,2,2,3,3,3,3};
__constant__ int c_tj[10] = {0,0,1,0,1,2,0,1,2,3};

__device__ __forceinline__ uint32_t smem_u32(const void* p) {
    uint32_t a;
    asm("{ .reg .u64 t; cvta.to.shared.u64 t, %1; cvt.u32.u64 %0, t; }"
        : "=r"(a) : "l"(p));
    return a;
}

// K1: M = diag(P)+sigma*I+rho*A^T A (packed lower). 64x64 tiles, 4x4 regs.
__global__ __launch_bounds__(256) void k1_buildM(const float* __restrict__ Pv,
                                                 const float* __restrict__ Av)
{
    int p = blockIdx.x, b = blockIdx.y;
    int i0 = c_ti[p] * 64, j0 = c_tj[p] * 64;
    __shared__ float As[16][64], Bs[16][64];
    const float* A = Av + (size_t)b * (MM * NN);
    float acc[4][4];
#pragma unroll
    for (int a = 0; a < 4; a++)
#pragma unroll
        for (int c = 0; c < 4; c++) acc[a][c] = 0.f;
    int t = threadIdx.x, tx = t & 15, ty = t >> 4;
    for (int k0 = 0; k0 < MM; k0 += 16) {
#pragma unroll
        for (int r = 0; r < 4; r++) {
            int idx = t + 256 * r, kk = idx >> 6, ii = idx & 63;
            As[kk][ii] = A[(k0 + kk) * NN + i0 + ii];
            Bs[kk][ii] = A[(k0 + kk) * NN + j0 + ii];
        }
        __syncthreads();
#pragma unroll
        for (int kk = 0; kk < 16; kk++) {
            float a[4], c[4];
#pragma unroll
            for (int x = 0; x < 4; x++) { a[x] = As[kk][ty + 16 * x]; c[x] = Bs[kk][tx + 16 * x]; }
#pragma unroll
            for (int ii = 0; ii < 4; ii++)
#pragma unroll
                for (int jj = 0; jj < 4; jj++) acc[ii][jj] = fmaf(a[ii], c[jj], acc[ii][jj]);
        }
        __syncthreads();
    }
    float* Mb = g_M + (size_t)b * TRI;
#pragma unroll
    for (int ii = 0; ii < 4; ii++) {
        int i = i0 + ty + 16 * ii;
#pragma unroll
        for (int jj = 0; jj < 4; jj++) {
            int j = j0 + tx + 16 * jj;
            if (j <= i) {
                float vv = RHO * acc[ii][jj];
                if (i == j) vv += Pv[b * NN + i] + SIGMA;
                Mb[offr(i) + j] = vv;
            }
        }
    }
}

// K23: fused Cholesky + triangular inverse, all in SMEM. Writes g_Linv only.
__global__ __launch_bounds__(1024) void k23_chol_inv()
{
    int b = blockIdx.x, tid = threadIdx.x;
    extern __shared__ float smf[];
    float* Ls  = smf;             // TRI
    float* col = smf + TRI;       // 256
    float* cb0 = col + 256;       // 32*256
    const float* Mb = g_M + (size_t)b * TRI;
    float* Lb = g_Linv + (size_t)b * TRI;
    for (int i = tid; i < TRI; i += 1024) Ls[i] = Mb[i];
    __syncthreads();
    int lane = tid & 31, w = tid >> 5;
    // ---- Cholesky (rank-1) ----
    for (int k = 0; k < 256; k++) {
        float dkk = Ls[offr(k) + k];
        float s = sqrtf(dkk), rinv = 1.0f / s;
        __syncthreads();
        for (int i = k + tid; i < 256; i += 1024) {
            if (i == k) { Ls[offr(k) + k] = s; col[k] = s; }
            else { float vv = Ls[offr(i) + k] * rinv; Ls[offr(i) + k] = vv; col[i] = vv; }
        }
        __syncthreads();
        for (int i = k + 1 + w; i < 256; i += 32) {
            float ci = col[i];
            float* row = Ls + offr(i);
            for (int j = k + 1 + lane; j <= i; j += 32) row[j] = fmaf(-ci, col[j], row[j]);
        }
        __syncthreads();
    }
    // ---- trinv: warp per column ----
    float* cb = cb0 + w * 256;
    for (int kc = w; kc < 256; kc += 32) {
        if (lane == 0) cb[kc] = 1.0f / Ls[offr(kc) + kc];
        __syncwarp();
        for (int i = kc + 1; i < 256; i++) {
            const float* row = Ls + offr(i);
            float s = 0.f;
            for (int j = kc + lane; j < i; j += 32) s = fmaf(row[j], cb[j], s);
#pragma unroll
            for (int o = 16; o; o >>= 1) s += __shfl_xor_sync(0xFFFFFFFFu, s, o);
            if (lane == 0) cb[i] = -s / row[i];
            __syncwarp();
        }
        for (int i = kc + lane; i < 256; i += 32) Lb[offr(i) + kc] = cb[i];
    }
}

// K4: Y[n][m] = sum_{j<=n} Linv[n][j]*A[m][j]
__global__ __launch_bounds__(256) void k4_Y(const float* __restrict__ Av)
{
    int b = blockIdx.z;
    int m0 = blockIdx.x * 64, n0 = blockIdx.y * 64;
    __shared__ float As[16][65], Bs[16][65];
    const float* Lb = g_Linv + (size_t)b * TRI;
    const float* A = Av + (size_t)b * (MM * NN);
    float acc[4][4];
#pragma unroll
    for (int a = 0; a < 4; a++)
#pragma unroll
        for (int c = 0; c < 4; c++) acc[a][c] = 0.f;
    int t = threadIdx.x, tx = t & 15, ty = t >> 4;
    int kmax = n0 + 64;
    for (int k0 = 0; k0 < kmax; k0 += 16) {
#pragma unroll
        for (int r = 0; r < 4; r++) {
            int idx = t + 256 * r, jj = idx & 15, nn = idx >> 4;
            int n = n0 + nn, j = k0 + jj;
            As[jj][nn] = (j <= n) ? Lb[offr(n) + j] : 0.f;
            Bs[jj][nn] = A[(m0 + nn) * NN + j];
        }
        __syncthreads();
#pragma unroll
        for (int jj = 0; jj < 16; jj++) {
            float a[4], c[4];
#pragma unroll
            for (int x = 0; x < 4; x++) { a[x] = As[jj][ty + 16 * x]; c[x] = Bs[jj][tx + 16 * x]; }
#pragma unroll
            for (int ii = 0; ii < 4; ii++)
#pragma unroll
                for (int cc = 0; cc < 4; cc++) acc[ii][cc] = fmaf(a[ii], c[cc], acc[ii][cc]);
        }
        __syncthreads();
    }
#pragma unroll
    for (int ii = 0; ii < 4; ii++) {
        int n = n0 + ty + 16 * ii;
#pragma unroll
        for (int cc = 0; cc < 4; cc++) {
            int m = m0 + tx + 16 * cc;
            g_Y[((size_t)b * NN + n) * MM + m] = acc[ii][cc];
        }
    }
}

// ---- K5 batched row group: dots first, then interleaved butterflies ----
template<int R0, int CNT>
__device__ __forceinline__ void row_group(int w, int lane,
    const float4* __restrict__ sY4, const float4* __restrict__ Yg4,
    const float4 ul[4], float4 acc[4], const float gre[8], float Sreg[8])
{
    float4 y[CNT][4];
#pragma unroll
    for (int k = 0; k < CNT; k++) {
        int n = w + 16 * (R0 + k);
        const float4* src = ((R0 + k) <= 4) ? (sY4 + (size_t)n * 128)
                                            : (Yg4 + (size_t)n * 128);
#pragma unroll
        for (int c = 0; c < 4; c++) y[k][c] = src[lane * 4 + c];
    }
    float s[CNT];
#pragma unroll
    for (int k = 0; k < CNT; k++) {
        float t = 0.f;
#pragma unroll
        for (int c = 0; c < 4; c++)
            t += y[k][c].x * ul[c].x + y[k][c].y * ul[c].y
               + y[k][c].z * ul[c].z + y[k][c].w * ul[c].w;
        s[k] = t;
    }
#pragma unroll
    for (int o = 16; o; o >>= 1)
#pragma unroll
        for (int k = 0; k < CNT; k++)
            s[k] += __shfl_xor_sync(0xFFFFFFFFu, s[k], o);
#pragma unroll
    for (int k = 0; k < CNT; k++) {
        s[k] -= gre[R0 + k];
        Sreg[R0 + k] = (1.0f - ALPHA) * Sreg[R0 + k] + ALPHA * s[k];
#pragma unroll
        for (int c = 0; c < 4; c++) {
            acc[c].x = fmaf(s[k], y[k][c].x, acc[c].x);
            acc[c].y = fmaf(s[k], y[k][c].y, acc[c].y);
            acc[c].z = fmaf(s[k], y[k][c].z, acc[c].z);
            acc[c].w = fmaf(s[k], y[k][c].w, acc[c].w);
        }
    }
}

// K5: 200 ADMM iterations. 2-CTA cluster per batch; 80/128 rows SMEM-resident.
// Single elected mbarrier arrive per iteration (count=1).
#define SM5_FLOATS (4 + RR * 512 + 16 * 512 + 4 * 512 + 2 * 512)
__global__ __cluster_dims__(2, 1, 1) __launch_bounds__(512, 1)
void k5_iter(const float* __restrict__ lv, const float* __restrict__ uv,
             const float* __restrict__ qv)
{
    cg::cluster_group cluster = cg::this_cluster();
    int b = blockIdx.x >> 1, half = blockIdx.x & 1;
    int tid = threadIdx.x, lane = tid & 31, w = tid >> 5;
    extern __shared__ float sm5[];
    float* mbf  = sm5;                    // 2 x u64 mbarriers
    float* sY   = sm5 + 4;                // RR*512
    float* red  = sY + RR * 512;          // 16*512
    float* sz   = red + 16 * 512;         // 512
    float* sy   = sz + 512;               // 512
    float* sl   = sy + 512;               // 512
    float* sub  = sl + 512;               // 512
    float* sbuf = sub + 512;              // 2*512 (peer writes here)

    uint32_t mb_u32 = smem_u32(mbf);
    if (tid == 0) {
        asm volatile("mbarrier.init.shared.b64 [%0], %1;" :: "r"(mb_u32), "r"(1) : "memory");
        asm volatile("mbarrier.init.shared.b64 [%0], %1;" :: "r"(mb_u32 + 8), "r"(1) : "memory");
    }

    const float* Yg = g_Y + ((size_t)b * NN + half * 128) * MM;
    const float4* Yg4 = (const float4*)Yg;
    for (int i = tid; i < RR * 128; i += 512)
        ((float4*)sY)[i] = Yg4[i];
    sz[tid] = 0.f; sy[tid] = 0.f;
    sl[tid] = lv[b * MM + tid]; sub[tid] = uv[b * MM + tid];

    // g for this warp's rows: g_n = sum_{j<=n} Linv[n][j] q[j]
    float Sreg[8], gre[8];
    {
        const float* Lb = g_Linv + (size_t)b * TRI;
        const float* qb = qv + b * NN;
#pragma unroll
        for (int r = 0; r < 8; r++) {
            int ng = half * 128 + w + 16 * r;
            const float* row = Lb + offr(ng);
            float s = 0.f;
            for (int j = lane; j <= ng; j += 32) s = fmaf(row[j], qb[j], s);
#pragma unroll
            for (int o = 16; o; o >>= 1) s += __shfl_xor_sync(0xFFFFFFFFu, s, o);
            gre[r] = s;
            Sreg[r] = 0.f;
        }
    }
    cluster.sync();   // barrier init + staging visible cluster-wide

    uint32_t peer = (uint32_t)(half ^ 1);
    float* peerbuf = cluster.map_shared_rank(sbuf, peer);
    const float4* sY4 = (const float4*)sY;
    const float4* z4 = (const float4*)sz;
    const float4* yv4 = (const float4*)sy;
    float4* redw = (float4*)(red + w * 512);

    for (int it = 0; it < ITERS; it++) {
        __syncthreads();
        float4 ul[4];
#pragma unroll
        for (int c = 0; c < 4; c++) {
            float4 zz = z4[lane * 4 + c], yy = yv4[lane * 4 + c];
            ul[c].x = RHO * zz.x - yy.x; ul[c].y = RHO * zz.y - yy.y;
            ul[c].z = RHO * zz.z - yy.z; ul[c].w = RHO * zz.w - yy.w;
        }
        float4 acc[4];
#pragma unroll
        for (int c = 0; c < 4; c++) acc[c] = make_float4(0.f, 0.f, 0.f, 0.f);

        row_group<0, 3>(w, lane, sY4, Yg4, ul, acc, gre, Sreg);
        row_group<3, 3>(w, lane, sY4, Yg4, ul, acc, gre, Sreg);
        row_group<6, 2>(w, lane, sY4, Yg4, ul, acc, gre, Sreg);

#pragma unroll
        for (int c = 0; c < 4; c++) redw[lane * 4 + c] = acc[c];
        __syncthreads();
        float mypart = 0.f;
#pragma unroll
        for (int w2 = 0; w2 < 16; w2++) mypart += red[w2 * 512 + tid];

        int slot = it & 1;
        uint32_t par = (uint32_t)((it >> 1) & 1);
        peerbuf[slot * 512 + tid] = mypart;           // DSMEM store
        __syncthreads();                              // all stores done CTA-wide
        if (tid == 0) {
            asm volatile("fence.acq_rel.cluster;" ::: "memory");
            asm volatile(
                "{ .reg .b32 rem; mapa.shared::cluster.u32 rem, %0, %1;\n\t"
                "mbarrier.arrive.release.cluster.shared::cluster.b64 _, [rem]; }"
                :: "r"(mb_u32 + 8 * slot), "r"(peer) : "memory");
        }
        {   // all threads acquire-wait on local mbarrier
            uint32_t addr = mb_u32 + 8 * slot, done;
            asm volatile(
                "{ .reg .pred p;\n\t"
                "mbarrier.try_wait.parity.acquire.cluster.shared::cta.b64 p, [%1], %2;\n\t"
                "selp.b32 %0, 1, 0, p; }"
                : "=r"(done) : "r"(addr), "r"(par) : "memory");
            if (!done) {
                asm volatile(
                    "{ .reg .pred P1;\n\t"
                    "WL_%=:\n\t"
                    "mbarrier.try_wait.parity.acquire.cluster.shared::cta.b64 P1, [%0], %1, 0x989680;\n\t"
                    "@P1 bra.uni WD_%=;\n\t"
                    "bra.uni WL_%=;\n\t"
                    "WD_%=: }"
                    :: "r"(addr), "r"(par) : "memory");
            }
        }
        float zt = mypart + sbuf[slot * 512 + tid];
        float zr = ALPHA * zt + (1.0f - ALPHA) * sz[tid];
        float zc = zr + sy[tid] * (1.0f / RHO);
        float zn = fminf(fmaxf(zc, sl[tid]), sub[tid]);
        sy[tid] = sy[tid] + RHO * (zr - zn);
        sz[tid] = zn;
    }
    if (lane == 0) {
#pragma unroll
        for (int r = 0; r < 8; r++)
            g_S[b * NN + half * 128 + w + 16 * r] = Sreg[r];
    }
    cluster.sync();   // don't exit while peer may still touch our smem
}

// K6: x = Linv^T * S  -> d_out
__global__ __launch_bounds__(256) void k6_final(float* __restrict__ out)
{
    int b = blockIdx.x, tid = threadIdx.x;
    int lane = tid & 31, w = tid >> 5;
    __shared__ float sS[NN];
    __shared__ float red6[8][NN];
    sS[tid] = g_S[b * NN + tid];
    __syncthreads();
    const float* Lb = g_Linv + (size_t)b * TRI;
    float acc[8];
#pragma unroll
    for (int c = 0; c < 8; c++) acc[c] = 0.f;
    for (int n = w; n < NN; n += 8) {
        const float* row = Lb + offr(n);
        float sv = sS[n];
#pragma unroll
        for (int c = 0; c < 8; c++) {
            int i = lane + 32 * c;
            if (i <= n) acc[c] = fmaf(sv, row[i], acc[c]);
        }
    }
#pragma unroll
    for (int c = 0; c < 8; c++) red6[w][lane + 32 * c] = acc[c];
    __syncthreads();
    float x = 0.f;
#pragma unroll
    for (int w2 = 0; w2 < 8; w2++) x += red6[w2][tid];
    out[b * NN + tid] = x;
}

extern "C" void kernel_launch(void* const* d_in, const int* in_sizes, int n_in,
                              void* d_out, int out_size)
{
    const float* P = (const float*)d_in[0];
    const float* q = (const float*)d_in[1];
    const float* A = (const float*)d_in[2];
    const float* l = (const float*)d_in[3];
    const float* u = (const float*)d_in[4];
    float* out = (float*)d_out;

    int smem_k23 = (TRI + 256 + 32 * 256) * 4;   // 165,376 B
    int smem_k5 = SM5_FLOATS * 4;                // 208,912 B
    cudaFuncSetAttribute(k23_chol_inv, cudaFuncAttributeMaxDynamicSharedMemorySize, smem_k23);
    cudaFuncSetAttribute(k5_iter, cudaFuncAttributeMaxDynamicSharedMemorySize, smem_k5);

    k1_buildM<<<dim3(10, BATCH), 256>>>(P, A);
    k23_chol_inv<<<BATCH, 1024, smem_k23>>>();
    k4_Y<<<dim3(8, 4, BATCH), 256>>>(A);
    k5_iter<<<BATCH * 2, 512, smem_k5>>>(l, u, q);
    k6_final<<<BATCH, 256>>>(out);
}